// round 3
// baseline (speedup 1.0000x reference)
#include <cuda_runtime.h>
#include <cuda_bf16.h>
#include <math.h>

// GptOssTopKRouter: logits = hidden[T,H] @ weight[E,H]^T + bias[E]
// then top-4 (sorted desc, ties -> smaller index) and softmax over the 4.
// Output: float32, scores [T,4] at offset 0, indices (as float) at out_size/2.
//
// Near-tie hardening: rows where adjacent gaps among the fp32 top-5 are
// < GAP_THRESH get their top-6 candidate logits recomputed in fp64 and
// re-ranked exactly, so index selection matches the exact fp32-input ranking.

#define TOPK 4
#define NCAND 6
#define TM 32      // rows per CTA
#define TN 128     // experts (all of E)
#define KT 32      // K tile
#define GAP_THRESH 1e-3f

__global__ __launch_bounds__(256, 4)
void router_kernel(const float* __restrict__ hidden,
                   const float* __restrict__ weight,
                   const float* __restrict__ bias,
                   float* __restrict__ out,
                   int T, int H, int E, int idx_base)
{
    __shared__ float As[KT][TM];     // [k][m]  4 KB
    __shared__ float Bs[KT][TN];     // [k][n] 16 KB  (reused as logits[32][128])

    const int tid  = threadIdx.x;
    const int warp = tid >> 5;
    const int lane = tid & 31;

    const int row0 = blockIdx.x * TM;

    const int m0 = warp * 4;
    const int n0 = lane * 4;

    float acc[4][4];
#pragma unroll
    for (int i = 0; i < 4; i++)
#pragma unroll
        for (int j = 0; j < 4; j++) acc[i][j] = 0.0f;

    float bfrag[4];
#pragma unroll
    for (int j = 0; j < 4; j++) bfrag[j] = bias[n0 + j];

    // A loader: m = tid/8 (0..31), kg = tid%8 -> float4 at k = kg*4
    const int a_m  = tid >> 3;
    const int a_kg = tid & 7;
    // B loader: kg = tid/32 (0..7), le = tid%32; experts e = le + 32*i
    const int b_kg = tid >> 5;
    const int b_le = tid & 31;

    const int ntiles = H / KT;   // H=2880 -> 90
    for (int t = 0; t < ntiles; t++) {
        const int kb = t * KT;

        float4 a4 = *reinterpret_cast<const float4*>(
            &hidden[(size_t)(row0 + a_m) * H + kb + a_kg * 4]);
        float4 w4[4];
#pragma unroll
        for (int i = 0; i < 4; i++) {
            int e = b_le + 32 * i;
            w4[i] = *reinterpret_cast<const float4*>(
                &weight[(size_t)e * H + kb + b_kg * 4]);
        }

        __syncthreads();

        As[a_kg * 4 + 0][a_m] = a4.x;
        As[a_kg * 4 + 1][a_m] = a4.y;
        As[a_kg * 4 + 2][a_m] = a4.z;
        As[a_kg * 4 + 3][a_m] = a4.w;
#pragma unroll
        for (int i = 0; i < 4; i++) {
            int e = b_le + 32 * i;
            Bs[b_kg * 4 + 0][e] = w4[i].x;
            Bs[b_kg * 4 + 1][e] = w4[i].y;
            Bs[b_kg * 4 + 2][e] = w4[i].z;
            Bs[b_kg * 4 + 3][e] = w4[i].w;
        }

        __syncthreads();

#pragma unroll
        for (int kk = 0; kk < KT; kk++) {
            float4 av = *reinterpret_cast<const float4*>(&As[kk][m0]);
            float4 bv = *reinterpret_cast<const float4*>(&Bs[kk][n0]);
            float a[4] = {av.x, av.y, av.z, av.w};
            float b[4] = {bv.x, bv.y, bv.z, bv.w};
#pragma unroll
            for (int i = 0; i < 4; i++)
#pragma unroll
                for (int j = 0; j < 4; j++)
                    acc[i][j] = fmaf(a[i], b[j], acc[i][j]);
        }
    }

    __syncthreads();

    // ---- write logits (+bias) into smem, reusing Bs as logits[32][128] ----
    float* logits = &Bs[0][0];
#pragma unroll
    for (int i = 0; i < 4; i++)
#pragma unroll
        for (int j = 0; j < 4; j++)
            logits[(m0 + i) * TN + (n0 + j)] = acc[i][j] + bfrag[j];

    __syncthreads();

    // ---- per-row top-6 + softmax; warp w handles rows 4w..4w+3 ----
#pragma unroll 1
    for (int rr = 0; rr < 4; rr++) {
        const int r = warp * 4 + rr;
        const int row = row0 + r;
        float v[4];
        bool taken[4] = {false, false, false, false};
#pragma unroll
        for (int j = 0; j < 4; j++) v[j] = logits[r * TN + lane + 32 * j];

        float topv[NCAND];
        int   topi[NCAND];
#pragma unroll 1
        for (int k = 0; k < NCAND; k++) {
            float bv = -INFINITY;
            int   bi = 0x7FFFFFFF;
#pragma unroll
            for (int j = 0; j < 4; j++) {
                if (!taken[j] && v[j] > bv) { bv = v[j]; bi = lane + 32 * j; }
            }
#pragma unroll
            for (int off = 16; off > 0; off >>= 1) {
                float ov = __shfl_xor_sync(0xFFFFFFFFu, bv, off);
                int   oi = __shfl_xor_sync(0xFFFFFFFFu, bi, off);
                if (ov > bv || (ov == bv && oi < bi)) { bv = ov; bi = oi; }
            }
            topv[k] = bv;   // after xor-reduction all lanes agree
            topi[k] = bi;
            if ((bi & 31) == lane) taken[bi >> 5] = true;
        }

        // gap check over adjacent pairs among top-5 (uniform across warp)
        bool need = (topv[0] - topv[1] < GAP_THRESH) ||
                    (topv[1] - topv[2] < GAP_THRESH) ||
                    (topv[2] - topv[3] < GAP_THRESH) ||
                    (topv[3] - topv[4] < GAP_THRESH);

        if (!need) {
            if (lane == 0) {
                float mx = topv[0];
                float e0 = expf(topv[0] - mx);
                float e1 = expf(topv[1] - mx);
                float e2 = expf(topv[2] - mx);
                float e3 = expf(topv[3] - mx);
                float inv = 1.0f / (e0 + e1 + e2 + e3);
                float* so = out + (size_t)row * TOPK;
                so[0] = e0 * inv; so[1] = e1 * inv; so[2] = e2 * inv; so[3] = e3 * inv;
                float* io = out + idx_base + (size_t)row * TOPK;
                io[0] = (float)topi[0]; io[1] = (float)topi[1];
                io[2] = (float)topi[2]; io[3] = (float)topi[3];
            }
        } else {
            // fp64 refinement of the 6 candidates (whole warp participates)
            const float* hrow = hidden + (size_t)row * H;
            double rv[NCAND];
#pragma unroll 1
            for (int c = 0; c < NCAND; c++) {
                const float* wrow = weight + (size_t)topi[c] * H;
                double acc64 = 0.0;
                for (int j = lane; j < H; j += 32)
                    acc64 = fma((double)hrow[j], (double)wrow[j], acc64);
#pragma unroll
                for (int off = 16; off > 0; off >>= 1)
                    acc64 += __shfl_xor_sync(0xFFFFFFFFu, acc64, off);
                rv[c] = acc64 + (double)bias[topi[c]];
            }
            if (lane == 0) {
                int ri[NCAND];
#pragma unroll
                for (int c = 0; c < NCAND; c++) ri[c] = topi[c];
                // selection sort: value desc, index asc on ties
#pragma unroll
                for (int a = 0; a < TOPK; a++) {
                    int best = a;
#pragma unroll
                    for (int b = a + 1; b < NCAND; b++) {
                        if (rv[b] > rv[best] ||
                            (rv[b] == rv[best] && ri[b] < ri[best])) best = b;
                    }
                    double tv = rv[a]; rv[a] = rv[best]; rv[best] = tv;
                    int    ti = ri[a]; ri[a] = ri[best]; ri[best] = ti;
                }
                double mx = rv[0];
                float e0 = expf((float)(rv[0] - mx));
                float e1 = expf((float)(rv[1] - mx));
                float e2 = expf((float)(rv[2] - mx));
                float e3 = expf((float)(rv[3] - mx));
                float inv = 1.0f / (e0 + e1 + e2 + e3);
                float* so = out + (size_t)row * TOPK;
                so[0] = e0 * inv; so[1] = e1 * inv; so[2] = e2 * inv; so[3] = e3 * inv;
                float* io = out + idx_base + (size_t)row * TOPK;
                io[0] = (float)ri[0]; io[1] = (float)ri[1];
                io[2] = (float)ri[2]; io[3] = (float)ri[3];
            }
        }
    }
}

extern "C" void kernel_launch(void* const* d_in, const int* in_sizes, int n_in,
                              void* d_out, int out_size)
{
    const float* hidden = (const float*)d_in[0];
    const float* weight = (const float*)d_in[1];
    const float* bias   = (const float*)d_in[2];
    float* out = (float*)d_out;

    const int E = in_sizes[2];                 // 128
    const int H = in_sizes[1] / E;             // 2880
    const int T = in_sizes[0] / H;             // 16384
    const int idx_base = out_size / 2;         // indices live in the second half

    dim3 grid(T / TM);
    dim3 block(256);
    router_kernel<<<grid, block>>>(hidden, weight, bias, out, T, H, E, idx_base);
}

// round 7
// speedup vs baseline: 2.2466x; 2.2466x over previous
#include <cuda_runtime.h>
#include <cuda_bf16.h>
#include <math.h>
#include <stdint.h>

// GptOssTopKRouter via legacy mma.sync (bf16x3 split emulating fp32 GEMM).
// logits = hidden[T,H] @ weight[E,H]^T + bias ; top-4 ; softmax over the 4.
// Output f32: scores [T,4] at 0, indices-as-float at out_size/2.
// Near-tie rows (adjacent top-5 gap < GAP_THRESH) re-ranked with fp64 dots.

#define TOPK 4
#define NCAND 6
#define GAP_THRESH 1e-3f

#define BM 128
#define BN 128
#define KC 32                 // k elements per chunk
#define LGS 132               // padded logits stride (floats)

// smem layout (bytes)
#define SM_BIAS     0                         // 512 B
#define SM_TILES    1024
#define TILE_BYTES  8192                      // 128 rows x 32 bf16 (64 B/row)
#define STAGE_BYTES (4*TILE_BYTES)            // Ahi,Alo,Bhi,Blo
#define SM_LOGITS   1024                      // aliases stages (after GEMM)
#define SMEM_TOTAL  (1024 + 128*LGS*4)        // 68608 > 1024+2*STAGE (66560)

// swizzled byte offset within a tile: 64B rows, 16B units c16 in 0..3
__device__ __forceinline__ uint32_t swz(int row, int c16) {
    return (uint32_t)(row * 64 + ((c16 ^ ((row >> 1) & 3)) << 4));
}

__device__ __forceinline__ uint32_t smem_u32(const void* p){
    uint32_t a;
    asm("{ .reg .u64 t; cvta.to.shared.u64 t, %1; cvt.u32.u64 %0, t; }":"=r"(a):"l"(p));
    return a;
}

__device__ __forceinline__ void ldsm4(uint32_t r[4], uint32_t addr){
    asm volatile("ldmatrix.sync.aligned.m8n8.x4.shared.b16 {%0,%1,%2,%3}, [%4];"
        : "=r"(r[0]),"=r"(r[1]),"=r"(r[2]),"=r"(r[3]) : "r"(addr));
}

__device__ __forceinline__ void mma_bf16(float d[4], const uint32_t a[4], const uint32_t b[2]){
    asm volatile("mma.sync.aligned.m16n8k16.row.col.f32.bf16.bf16.f32 "
        "{%0,%1,%2,%3}, {%4,%5,%6,%7}, {%8,%9}, {%0,%1,%2,%3};"
        : "+f"(d[0]),"+f"(d[1]),"+f"(d[2]),"+f"(d[3])
        : "r"(a[0]),"r"(a[1]),"r"(a[2]),"r"(a[3]), "r"(b[0]),"r"(b[1]));
}

// split 8 fp32 into packed bf16x2 hi[4] / lo[4] (low half = even element)
__device__ __forceinline__ void split8(float4 f0, float4 f1, uint32_t hi[4], uint32_t lo[4]){
    float f[8] = {f0.x,f0.y,f0.z,f0.w,f1.x,f1.y,f1.z,f1.w};
#pragma unroll
    for (int i = 0; i < 4; i++) {
        uint32_t hp;
        asm("cvt.rn.bf16x2.f32 %0, %1, %2;" : "=r"(hp) : "f"(f[2*i+1]), "f"(f[2*i]));
        float h0 = __uint_as_float(hp << 16);
        float h1 = __uint_as_float(hp & 0xFFFF0000u);
        float l0 = f[2*i]   - h0;
        float l1 = f[2*i+1] - h1;
        uint32_t lp;
        asm("cvt.rn.bf16x2.f32 %0, %1, %2;" : "=r"(lp) : "f"(l1), "f"(l0));
        hi[i] = hp; lo[i] = lp;
    }
}

__global__ __launch_bounds__(256, 1)
void router_mma_kernel(const float* __restrict__ hidden,
                       const float* __restrict__ weight,
                       const float* __restrict__ bias,
                       float* __restrict__ out,
                       int T, int H, int E, int idx_base)
{
    extern __shared__ char smem[];
    float* bias_s = (float*)(smem + SM_BIAS);
    float* logits = (float*)(smem + SM_LOGITS);
    const uint32_t sbase = smem_u32(smem);

    const int tid  = threadIdx.x;
    const int wid  = tid >> 5;
    const int lane = tid & 31;
    const int row0 = blockIdx.x * BM;

    if (tid < BN) bias_s[tid] = bias[tid];

    // loader mapping: idx = tid + 256*s (s=0,1): row = idx>>2 (0..127), quarter q = idx&3
    const int lrow = tid >> 2;       // row for s=0 ; s=1 adds 64
    const int lq   = tid & 3;        // which 8-float segment of the 32-elem row

    // warp tile: 4x2 warps, each 32 (M) x 64 (N)
    const int wm = (wid & 3) * 32;
    const int wn = (wid >> 2) * 64;

    float d[2][8][4];
#pragma unroll
    for (int mt = 0; mt < 2; mt++)
#pragma unroll
        for (int nt = 0; nt < 8; nt++)
#pragma unroll
            for (int k = 0; k < 4; k++) d[mt][nt][k] = 0.0f;

    float4 stg[8];

    // prologue: LDG chunk 0
#pragma unroll
    for (int s = 0; s < 2; s++) {
        int r = lrow + 64 * s;
        const float* ap = &hidden[(size_t)(row0 + r) * H + lq * 8];
        const float* bp = &weight[(size_t)r * H + lq * 8];
        stg[s*2+0] = *reinterpret_cast<const float4*>(ap);
        stg[s*2+1] = *reinterpret_cast<const float4*>(ap + 4);
        stg[4+s*2+0] = *reinterpret_cast<const float4*>(bp);
        stg[4+s*2+1] = *reinterpret_cast<const float4*>(bp + 4);
    }

    const int nch = H / KC;    // 90
    for (int t = 0; t < nch; t++) {
        char* stage_p = smem + SM_TILES + (t & 1) * STAGE_BYTES;
        const uint32_t stage_a = sbase + SM_TILES + (t & 1) * STAGE_BYTES;

        // ---- convert + STS (A hi/lo, B hi/lo) ----
#pragma unroll
        for (int s = 0; s < 2; s++) {
            int r = lrow + 64 * s;
            uint32_t off = swz(r, lq);
            uint32_t hi[4], lo[4];
            split8(stg[s*2+0], stg[s*2+1], hi, lo);
            *reinterpret_cast<uint4*>(stage_p + 0*TILE_BYTES + off) = make_uint4(hi[0],hi[1],hi[2],hi[3]);
            *reinterpret_cast<uint4*>(stage_p + 1*TILE_BYTES + off) = make_uint4(lo[0],lo[1],lo[2],lo[3]);
            split8(stg[4+s*2+0], stg[4+s*2+1], hi, lo);
            *reinterpret_cast<uint4*>(stage_p + 2*TILE_BYTES + off) = make_uint4(hi[0],hi[1],hi[2],hi[3]);
            *reinterpret_cast<uint4*>(stage_p + 3*TILE_BYTES + off) = make_uint4(lo[0],lo[1],lo[2],lo[3]);
        }

        // ---- prefetch next chunk ----
        if (t + 1 < nch) {
            int kb = (t + 1) * KC;
#pragma unroll
            for (int s = 0; s < 2; s++) {
                int r = lrow + 64 * s;
                const float* ap = &hidden[(size_t)(row0 + r) * H + kb + lq * 8];
                const float* bp = &weight[(size_t)r * H + kb + lq * 8];
                stg[s*2+0] = *reinterpret_cast<const float4*>(ap);
                stg[s*2+1] = *reinterpret_cast<const float4*>(ap + 4);
                stg[4+s*2+0] = *reinterpret_cast<const float4*>(bp);
                stg[4+s*2+1] = *reinterpret_cast<const float4*>(bp + 4);
            }
        }

        __syncthreads();

        // ---- MMA phase: 2 k16 steps ----
#pragma unroll
        for (int s2 = 0; s2 < 2; s2++) {
            uint32_t Ah[2][4], Al[2][4], Bh[4][4], Bl[4][4];
#pragma unroll
            for (int mt = 0; mt < 2; mt++) {
                int r = wm + mt * 16 + (lane & 15);
                int c16 = 2 * s2 + (lane >> 4);
                uint32_t ao = swz(r, c16);
                ldsm4(Ah[mt], stage_a + 0*TILE_BYTES + ao);
                ldsm4(Al[mt], stage_a + 1*TILE_BYTES + ao);
            }
#pragma unroll
            for (int p = 0; p < 4; p++) {
                int nr = wn + p * 16 + (lane & 7) + ((lane >> 4) & 1) * 8;
                int c16 = 2 * s2 + ((lane >> 3) & 1);
                uint32_t bo = swz(nr, c16);
                ldsm4(Bh[p], stage_a + 2*TILE_BYTES + bo);
                ldsm4(Bl[p], stage_a + 3*TILE_BYTES + bo);
            }
            // hi*hi
#pragma unroll
            for (int mt = 0; mt < 2; mt++)
#pragma unroll
                for (int nt = 0; nt < 8; nt++)
                    mma_bf16(d[mt][nt], Ah[mt], &Bh[nt >> 1][(nt & 1) * 2]);
            // hi*lo
#pragma unroll
            for (int mt = 0; mt < 2; mt++)
#pragma unroll
                for (int nt = 0; nt < 8; nt++)
                    mma_bf16(d[mt][nt], Ah[mt], &Bl[nt >> 1][(nt & 1) * 2]);
            // lo*hi
#pragma unroll
            for (int mt = 0; mt < 2; mt++)
#pragma unroll
                for (int nt = 0; nt < 8; nt++)
                    mma_bf16(d[mt][nt], Al[mt], &Bh[nt >> 1][(nt & 1) * 2]);
        }
    }

    __syncthreads();   // all ldmatrix done before logits alias the stage buffers

    // ---- accum (+bias) -> smem logits[128][LGS] ----
#pragma unroll
    for (int mt = 0; mt < 2; mt++)
#pragma unroll
        for (int nt = 0; nt < 8; nt++) {
            int m = wm + mt * 16 + (lane >> 2);
            int n = wn + nt * 8 + 2 * (lane & 3);
            logits[m * LGS + n]         = d[mt][nt][0] + bias_s[n];
            logits[m * LGS + n + 1]     = d[mt][nt][1] + bias_s[n + 1];
            logits[(m + 8) * LGS + n]     = d[mt][nt][2] + bias_s[n];
            logits[(m + 8) * LGS + n + 1] = d[mt][nt][3] + bias_s[n + 1];
        }
    __syncthreads();

    // ---- per-row top-6 + softmax; warp w handles rows 16w..16w+15 ----
#pragma unroll 1
    for (int rr = 0; rr < 16; rr++) {
        const int r = wid * 16 + rr;
        const int row = row0 + r;
        float v[4];
        bool taken[4] = {false, false, false, false};
#pragma unroll
        for (int j = 0; j < 4; j++) v[j] = logits[r * LGS + lane + 32 * j];

        float topv[NCAND];
        int   topi[NCAND];
#pragma unroll 1
        for (int k = 0; k < NCAND; k++) {
            float bv = -INFINITY;
            int   bi = 0x7FFFFFFF;
#pragma unroll
            for (int j = 0; j < 4; j++)
                if (!taken[j] && v[j] > bv) { bv = v[j]; bi = lane + 32 * j; }
#pragma unroll
            for (int off = 16; off > 0; off >>= 1) {
                float ov = __shfl_xor_sync(0xFFFFFFFFu, bv, off);
                int   oi = __shfl_xor_sync(0xFFFFFFFFu, bi, off);
                if (ov > bv || (ov == bv && oi < bi)) { bv = ov; bi = oi; }
            }
            topv[k] = bv;
            topi[k] = bi;
            if ((bi & 31) == lane) taken[bi >> 5] = true;
        }

        bool need = (topv[0]-topv[1] < GAP_THRESH) || (topv[1]-topv[2] < GAP_THRESH) ||
                    (topv[2]-topv[3] < GAP_THRESH) || (topv[3]-topv[4] < GAP_THRESH);

        if (!need) {
            if (lane == 0) {
                float mx = topv[0];
                float e0 = expf(topv[0]-mx), e1 = expf(topv[1]-mx);
                float e2 = expf(topv[2]-mx), e3 = expf(topv[3]-mx);
                float inv = 1.0f / (e0+e1+e2+e3);
                float* so = out + (size_t)row * TOPK;
                so[0]=e0*inv; so[1]=e1*inv; so[2]=e2*inv; so[3]=e3*inv;
                float* io = out + idx_base + (size_t)row * TOPK;
                io[0]=(float)topi[0]; io[1]=(float)topi[1];
                io[2]=(float)topi[2]; io[3]=(float)topi[3];
            }
        } else {
            // fp64 refinement of the 6 candidates (whole warp participates)
            const float* hrow = hidden + (size_t)row * H;
            double rv[NCAND];
#pragma unroll 1
            for (int c = 0; c < NCAND; c++) {
                const float* wrow = weight + (size_t)topi[c] * H;
                double s0 = 0.0, s1 = 0.0;
                for (int j = lane; j < H; j += 64) {
                    s0 = fma((double)hrow[j],      (double)wrow[j],      s0);
                    s1 = fma((double)hrow[j + 32], (double)wrow[j + 32], s1);
                }
                double acc = s0 + s1;
#pragma unroll
                for (int off = 16; off > 0; off >>= 1)
                    acc += __shfl_xor_sync(0xFFFFFFFFu, acc, off);
                rv[c] = acc + (double)bias[topi[c]];
            }
            if (lane == 0) {
                int ri[NCAND];
#pragma unroll
                for (int c = 0; c < NCAND; c++) ri[c] = topi[c];
#pragma unroll
                for (int a = 0; a < TOPK; a++) {
                    int best = a;
#pragma unroll
                    for (int b = a + 1; b < NCAND; b++)
                        if (rv[b] > rv[best] || (rv[b] == rv[best] && ri[b] < ri[best])) best = b;
                    double tvv = rv[a]; rv[a] = rv[best]; rv[best] = tvv;
                    int    tii = ri[a]; ri[a] = ri[best]; ri[best] = tii;
                }
                double mx = rv[0];
                float e0 = expf((float)(rv[0]-mx)), e1 = expf((float)(rv[1]-mx));
                float e2 = expf((float)(rv[2]-mx)), e3 = expf((float)(rv[3]-mx));
                float inv = 1.0f / (e0+e1+e2+e3);
                float* so = out + (size_t)row * TOPK;
                so[0]=e0*inv; so[1]=e1*inv; so[2]=e2*inv; so[3]=e3*inv;
                float* io = out + idx_base + (size_t)row * TOPK;
                io[0]=(float)ri[0]; io[1]=(float)ri[1]; io[2]=(float)ri[2]; io[3]=(float)ri[3];
            }
        }
    }
}

extern "C" void kernel_launch(void* const* d_in, const int* in_sizes, int n_in,
                              void* d_out, int out_size)
{
    const float* hidden = (const float*)d_in[0];
    const float* weight = (const float*)d_in[1];
    const float* bias   = (const float*)d_in[2];
    float* out = (float*)d_out;

    const int E = in_sizes[2];                 // 128
    const int H = in_sizes[1] / E;             // 2880
    const int T = in_sizes[0] / H;             // 16384
    const int idx_base = out_size / 2;

    cudaFuncSetAttribute(router_mma_kernel,
                         cudaFuncAttributeMaxDynamicSharedMemorySize, SMEM_TOTAL);
    dim3 grid(T / BM);     // 128
    dim3 block(256);
    router_mma_kernel<<<grid, block, SMEM_TOTAL>>>(hidden, weight, bias, out, T, H, E, idx_base);
}